// round 9
// baseline (speedup 1.0000x reference)
#include <cuda_runtime.h>
#include <cuda_bf16.h>
#include <math.h>
#include <stdint.h>

#define BATCH 2
#define SEQ   2048
#define DMODEL 1024
#define NHEAD 16
#define HDIM  64
#define ROWS  (BATCH*SEQ)          // 4096
#define QKV_N (3*DMODEL)           // 3072

typedef __nv_bfloat16 bf;

// ---------------------------------------------------------------------------
// Device scratch
// ---------------------------------------------------------------------------
__device__ bf g_xhi[(size_t)ROWS * DMODEL];
__device__ bf g_xlo[(size_t)ROWS * DMODEL];
__device__ bf g_wqh[(size_t)QKV_N * DMODEL];   // W_qkv^T [3072][1024]
__device__ bf g_wql[(size_t)QKV_N * DMODEL];
__device__ bf g_woh[(size_t)DMODEL * DMODEL];  // W_out^T [1024][1024]
__device__ bf g_wol[(size_t)DMODEL * DMODEL];
__device__ bf g_chi[(size_t)ROWS * DMODEL];    // ctx hi/lo [row][1024]
__device__ bf g_clo[(size_t)ROWS * DMODEL];
// q/k/v split, layout [b][h][s][d]
__device__ bf g_qh[(size_t)BATCH * NHEAD * SEQ * HDIM];
__device__ bf g_ql[(size_t)BATCH * NHEAD * SEQ * HDIM];
__device__ bf g_kh[(size_t)BATCH * NHEAD * SEQ * HDIM];
__device__ bf g_kl[(size_t)BATCH * NHEAD * SEQ * HDIM];
__device__ bf g_vh[(size_t)BATCH * NHEAD * SEQ * HDIM];
__device__ bf g_vl[(size_t)BATCH * NHEAD * SEQ * HDIM];

// ---------------------------------------------------------------------------
// PTX helpers
// ---------------------------------------------------------------------------
__device__ __forceinline__ uint32_t smem_u32(const void* p) {
    uint32_t a;
    asm("{ .reg .u64 t; cvta.to.shared.u64 t, %1; cvt.u32.u64 %0, t; }" : "=r"(a) : "l"(p));
    return a;
}
#define CP16(sm, gm) asm volatile("cp.async.cg.shared.global [%0], [%1], 16;" :: "r"(sm), "l"(gm))
#define CP_COMMIT()  asm volatile("cp.async.commit_group;" ::: "memory")
#define CP_WAIT2()   asm volatile("cp.async.wait_group 2;" ::: "memory")
#define CP_WAIT1()   asm volatile("cp.async.wait_group 1;" ::: "memory")
#define CP_WAIT0()   asm volatile("cp.async.wait_group 0;" ::: "memory")

__device__ __forceinline__ void ldsm4(uint32_t* r, uint32_t addr) {
    asm volatile("ldmatrix.sync.aligned.m8n8.x4.shared.b16 {%0,%1,%2,%3}, [%4];"
                 : "=r"(r[0]), "=r"(r[1]), "=r"(r[2]), "=r"(r[3]) : "r"(addr));
}
__device__ __forceinline__ void ldsm4t(uint32_t* r, uint32_t addr) {
    asm volatile("ldmatrix.sync.aligned.m8n8.x4.trans.shared.b16 {%0,%1,%2,%3}, [%4];"
                 : "=r"(r[0]), "=r"(r[1]), "=r"(r[2]), "=r"(r[3]) : "r"(addr));
}
__device__ __forceinline__ void mma16816(float* c, const uint32_t* a, const uint32_t* b) {
    asm volatile(
        "mma.sync.aligned.m16n8k16.row.col.f32.bf16.bf16.f32 "
        "{%0,%1,%2,%3}, {%4,%5,%6,%7}, {%8,%9}, {%0,%1,%2,%3};"
        : "+f"(c[0]), "+f"(c[1]), "+f"(c[2]), "+f"(c[3])
        : "r"(a[0]), "r"(a[1]), "r"(a[2]), "r"(a[3]), "r"(b[0]), "r"(b[1]));
}
__device__ __forceinline__ float ex2(float x) {
    float y;
    asm("ex2.approx.f32 %0, %1;" : "=f"(y) : "f"(x));
    return y;
}
__device__ __forceinline__ uint32_t packbf(float x, float y) {
    __nv_bfloat162 t = __float22bfloat162_rn(make_float2(x, y));  // x -> low half
    return *(uint32_t*)&t;
}
__device__ __forceinline__ void split2(float x, float y, uint32_t& h, uint32_t& l) {
    h = packbf(x, y);
    float hx = __uint_as_float(h << 16);
    float hy = __uint_as_float(h & 0xffff0000u);
    l = packbf(x - hx, y - hy);
}

// ---------------------------------------------------------------------------
// Fused pre-pass: one launch does x-decomp + both weight transpose-decomps.
// blocks [0,4096)        : x elementwise split (vector4)
// blocks [4096,7168)     : W_qkv^T split (32x32 tiles)
// blocks [7168,8192)     : W_out^T split
// ---------------------------------------------------------------------------
__global__ __launch_bounds__(256) void prep_kernel(
    const float* __restrict__ x, const float* __restrict__ Wq,
    const float* __restrict__ Wo,
    bf* __restrict__ xhi, bf* __restrict__ xlo,
    bf* __restrict__ wqh, bf* __restrict__ wql,
    bf* __restrict__ woh, bf* __restrict__ wol)
{
    __shared__ float t[32][33];
    const int blk = blockIdx.x, tid = threadIdx.x;

    if (blk < 4096) {
        int i = blk * 256 + tid;   // exactly covers ROWS*DMODEL/4
        float4 v = ((const float4*)x)[i];
        uint32_t h0, l0, h1, l1;
        split2(v.x, v.y, h0, l0);
        split2(v.z, v.w, h1, l1);
        *(uint2*)(xhi + 4 * (size_t)i) = make_uint2(h0, h1);
        *(uint2*)(xlo + 4 * (size_t)i) = make_uint2(l0, l1);
        return;
    }

    const float* W; bf *hi, *lo;
    int K, N, bx, by;
    if (blk < 7168) {
        int idx = blk - 4096;           // grid (96, 32)
        W = Wq; hi = wqh; lo = wql; K = DMODEL; N = QKV_N;
        bx = idx % 96; by = idx / 96;
    } else {
        int idx = blk - 7168;           // grid (32, 32)
        W = Wo; hi = woh; lo = wol; K = DMODEL; N = DMODEL;
        bx = idx & 31; by = idx >> 5;
    }
    const int tx = tid & 31, ty = tid >> 5;  // 32 x 8
    const int n0 = bx * 32, k0 = by * 32;
    #pragma unroll
    for (int i = 0; i < 4; i++)
        t[ty + i * 8][tx] = W[(size_t)(k0 + ty + i * 8) * N + n0 + tx];
    __syncthreads();
    #pragma unroll
    for (int i = 0; i < 4; i++) {
        float v = t[tx][ty + i * 8];
        bf h = __float2bfloat16(v);
        bf l = __float2bfloat16(v - __bfloat162float(h));
        size_t o = (size_t)(n0 + ty + i * 8) * K + k0 + tx;
        hi[o] = h; lo[o] = l;
    }
}

// ---------------------------------------------------------------------------
// Tensor-core GEMM via mma.sync, bf16 3-MMA split, fragment-pipelined
// (R6/R8 proven config: 242-254us, tensor 57.5%).
// 512 threads, 16 warps (4x4), warp tile 32x32, BK=32, 4-stage ring, wait2.
// ---------------------------------------------------------------------------
#define GK 32
#define GROW 80
#define GSUB (128 * GROW)
#define GSTAGE (4 * GSUB)     // 40960
#define GNBUF 4
#define GM_DYN_BYTES (GNBUF * GSTAGE + 256)

__device__ __forceinline__ void gm_load_stage(
    uint32_t buf, const bf* gah, const bf* gal, const bf* gbh, const bf* gbl,
    int K, int tid)
{
    int row = tid >> 2, col = tid & 3;
    uint32_t so = (uint32_t)(row * GROW + col * 16);
    size_t g = (size_t)row * K + (size_t)col * 8;
    CP16(buf + so,            gah + g);
    CP16(buf + GSUB + so,     gal + g);
    CP16(buf + 2 * GSUB + so, gbh + g);
    CP16(buf + 3 * GSUB + so, gbl + g);
}

// fr layout: [0..7]=Ah(2 tiles), [8..15]=Al, [16..23]=Bh, [24..31]=Bl
__device__ __forceinline__ void ld_frags(uint32_t* fr, uint32_t sb,
                                         uint32_t a_off, uint32_t b_off, uint32_t ko)
{
    ldsm4(fr + 0,  sb + a_off + ko);
    ldsm4(fr + 4,  sb + a_off + 16u * GROW + ko);
    ldsm4(fr + 8,  sb + GSUB + a_off + ko);
    ldsm4(fr + 12, sb + GSUB + a_off + 16u * GROW + ko);
    ldsm4(fr + 16, sb + 2u * GSUB + b_off + ko);
    ldsm4(fr + 20, sb + 2u * GSUB + b_off + 16u * GROW + ko);
    ldsm4(fr + 24, sb + 3u * GSUB + b_off + ko);
    ldsm4(fr + 28, sb + 3u * GSUB + b_off + 16u * GROW + ko);
}

__device__ __forceinline__ void mma_frags(float acc[2][4][4], const uint32_t* fr)
{
    const uint32_t* ah = fr;
    const uint32_t* al = fr + 8;
    const uint32_t* bh = fr + 16;
    const uint32_t* bl = fr + 24;
    #pragma unroll
    for (int i = 0; i < 2; i++)
        #pragma unroll
        for (int j = 0; j < 4; j++) {
            const uint32_t* bhj = bh + (j >> 1) * 4 + (j & 1) * 2;
            const uint32_t* blj = bl + (j >> 1) * 4 + (j & 1) * 2;
            mma16816(acc[i][j], ah + i * 4, bhj);
            mma16816(acc[i][j], ah + i * 4, blj);
            mma16816(acc[i][j], al + i * 4, bhj);
        }
}

template<int EPI>
__global__ __launch_bounds__(512, 1) void gemm_hmma_x3(
    const bf* __restrict__ Ah, const bf* __restrict__ Al,
    const bf* __restrict__ Bh, const bf* __restrict__ Bl,
    const float* __restrict__ bias, float* __restrict__ C,
    bf* __restrict__ oqh, bf* __restrict__ oql,
    bf* __restrict__ okh, bf* __restrict__ okl,
    bf* __restrict__ ovh, bf* __restrict__ ovl,
    int M, int N, int K)
{
    extern __shared__ __align__(128) char dynsm[];
    const uint32_t smbase = smem_u32(dynsm);

    const int tid = threadIdx.x;
    const int wid = tid >> 5, lane = tid & 31;
    const int wr = wid >> 2, wc = wid & 3;          // warp grid 4 x 4
    const int m0 = blockIdx.y * 128, n0 = blockIdx.x * 128;

    const bf* ah0 = Ah + (size_t)m0 * K;
    const bf* al0 = Al + (size_t)m0 * K;
    const bf* bh0 = Bh + (size_t)n0 * K;
    const bf* bl0 = Bl + (size_t)n0 * K;

    const uint32_t a_off = (uint32_t)((wr * 32 + (lane & 15)) * GROW + (lane >> 4) * 16);
    const uint32_t b_off = (uint32_t)((wc * 32 + (lane >> 4) * 8 + (lane & 7)) * GROW
                                      + (((lane & 15) >> 3) * 16));

    float acc[2][4][4];
    #pragma unroll
    for (int i = 0; i < 2; i++)
        #pragma unroll
        for (int j = 0; j < 4; j++)
            #pragma unroll
            for (int r = 0; r < 4; r++) acc[i][j][r] = 0.f;

    const int NS = K / GK;   // 32

    gm_load_stage(smbase,              ah0,          al0,          bh0,          bl0,          K, tid);
    CP_COMMIT();
    gm_load_stage(smbase + GSTAGE,     ah0 + GK,     al0 + GK,     bh0 + GK,     bl0 + GK,     K, tid);
    CP_COMMIT();
    gm_load_stage(smbase + 2 * GSTAGE, ah0 + 2 * GK, al0 + 2 * GK, bh0 + 2 * GK, bl0 + 2 * GK, K, tid);
    CP_COMMIT();

    for (int s = 0; s < NS; s++) {
        CP_WAIT2();
        __syncthreads();

        const uint32_t sb = smbase + (uint32_t)(s & 3) * GSTAGE;
        uint32_t f0[32], f1[32];
        ld_frags(f0, sb, a_off, b_off, 0);     // kk0 fragments first

        int t = s + 3;                          // then global prefetch
        if (t < NS)
            gm_load_stage(smbase + (uint32_t)(t & 3) * GSTAGE,
                          ah0 + (size_t)t * GK, al0 + (size_t)t * GK,
                          bh0 + (size_t)t * GK, bl0 + (size_t)t * GK, K, tid);
        CP_COMMIT();

        ld_frags(f1, sb, a_off, b_off, 32);    // kk1 fragments before any mma

        mma_frags(acc, f0);
        mma_frags(acc, f1);
    }

    const int er = m0 + wr * 32 + (lane >> 2);
    const int ec = n0 + wc * 32 + 2 * (lane & 3);

    if (EPI == 0) {
        #pragma unroll
        for (int i = 0; i < 2; i++)
            #pragma unroll
            for (int j = 0; j < 4; j++) {
                int r = er + i * 16, c = ec + j * 8;
                *(float2*)(C + (size_t)r * N + c) =
                    make_float2(acc[i][j][0], acc[i][j][1]);
                *(float2*)(C + (size_t)(r + 8) * N + c) =
                    make_float2(acc[i][j][2], acc[i][j][3]);
            }
    } else {
        const int part = ec >> 10;
        bf *dh, *dl;
        if (part == 0)      { dh = oqh; dl = oql; }
        else if (part == 1) { dh = okh; dl = okl; }
        else                { dh = ovh; dl = ovl; }
        // q scale folded in LOG2 domain: 1/sqrt(64) * log2(e)
        const float sc = (part == 0) ? 0.18033688f : 1.0f;
        #pragma unroll
        for (int i = 0; i < 2; i++)
            #pragma unroll
            for (int j = 0; j < 4; j++) {
                int r = er + i * 16, c = ec + j * 8;
                int hh = (c >> 6) & 15, d = c & 63;
                float b0 = bias[c], b1 = bias[c + 1];
                uint32_t ph, pl;
                split2((acc[i][j][0] + b0) * sc, (acc[i][j][1] + b1) * sc, ph, pl);
                size_t off = (((size_t)(r >> 11) * NHEAD + hh) * SEQ + (r & 2047)) * HDIM + d;
                *(uint32_t*)(dh + off) = ph;
                *(uint32_t*)(dl + off) = pl;
                split2((acc[i][j][2] + b0) * sc, (acc[i][j][3] + b1) * sc, ph, pl);
                int r2 = r + 8;
                off = (((size_t)(r2 >> 11) * NHEAD + hh) * SEQ + (r2 & 2047)) * HDIM + d;
                *(uint32_t*)(dh + off) = ph;
                *(uint32_t*)(dl + off) = pl;
            }
    }
}

// ---------------------------------------------------------------------------
// HMMA flash attention, log2-domain softmax, 32 q-rows per warp.
// CTA = 256 q rows x one (b,h); 8 warps; warp = 32q (2 MMA tiles) x 64 keys.
// K/V 64-key tiles, 3-stage cp.async ring; warp-level causal tile skipping.
// ---------------------------------------------------------------------------
#define AROW 144
#define AQ_BYTES (256 * AROW)              // 36864 per q array (hi / lo)
#define AKV_BYTES (64 * AROW)              // 9216
#define AST (4 * AKV_BYTES)                // 36864
#define ATT_SMEM (2 * AQ_BYTES + 3 * AST)  // 184320

__device__ __forceinline__ void att_load_kv(
    uint32_t base, const bf* khp, const bf* klp, const bf* vhp, const bf* vlp,
    int kt, int tid)
{
    #pragma unroll
    for (int i = 0; i < 2; i++) {
        int c = i * 256 + tid;
        int row = c >> 3, col = c & 7;
        uint32_t so = (uint32_t)(row * AROW + col * 16);
        size_t g = (size_t)(kt * 64 + row) * HDIM + col * 8;
        CP16(base + so,                   khp + g);
        CP16(base + AKV_BYTES + so,       klp + g);
        CP16(base + 2 * AKV_BYTES + so,   vhp + g);
        CP16(base + 3 * AKV_BYTES + so,   vlp + g);
    }
}

__global__ __launch_bounds__(256, 1) void flash_hmma(
    const bf* __restrict__ qh, const bf* __restrict__ ql,
    const bf* __restrict__ kh, const bf* __restrict__ kl,
    const bf* __restrict__ vh, const bf* __restrict__ vl,
    bf* __restrict__ chi, bf* __restrict__ clo)
{
    extern __shared__ __align__(128) char asmbuf[];
    const uint32_t sb = smem_u32(asmbuf);
    const int tid = threadIdx.x, wid = tid >> 5, lane = tid & 31;
    const int qt = 7 - (int)blockIdx.x;        // longest first
    const int h = blockIdx.y, b = blockIdx.z;
    const int q0 = qt * 256;
    const int ktmax = 4 * qt + 3;

    const size_t headoff = ((size_t)b * NHEAD + h) * SEQ * HDIM;
    const bf* qhp = qh + headoff + (size_t)q0 * HDIM;
    const bf* qlp = ql + headoff + (size_t)q0 * HDIM;
    const bf* khp = kh + headoff;
    const bf* klp = kl + headoff;
    const bf* vhp = vh + headoff;
    const bf* vlp = vl + headoff;

    // Q tiles (hi/lo): 256 rows x 8 chunks each
    #pragma unroll
    for (int i = 0; i < 8; i++) {
        int c = i * 256 + tid;
        int row = c >> 3, col = c & 7;
        uint32_t so = (uint32_t)(row * AROW + col * 16);
        size_t g = (size_t)row * HDIM + col * 8;
        CP16(sb + so,            qhp + g);
        CP16(sb + AQ_BYTES + so, qlp + g);
    }
    att_load_kv(sb + 2 * AQ_BYTES, khp, klp, vhp, vlp, 0, tid);
    CP_COMMIT();
    att_load_kv(sb + 2 * AQ_BYTES + AST, khp, klp, vhp, vlp, 1, tid);
    CP_COMMIT();

    float s[2][8][4], acc[2][8][4];
    float mv[2][2], lv[2][2];
    #pragma unroll
    for (int i = 0; i < 2; i++) {
        mv[i][0] = mv[i][1] = -1e30f;
        lv[i][0] = lv[i][1] = 0.f;
        #pragma unroll
        for (int nc = 0; nc < 8; nc++)
            acc[i][nc][0] = acc[i][nc][1] = acc[i][nc][2] = acc[i][nc][3] = 0.f;
    }
    uint32_t qfh[2][16];   // hi Q fragments persistent; lo reloaded per ks

    const uint32_t a_off = (uint32_t)((wid * 32 + (lane & 15)) * AROW + (lane >> 4) * 16);
    const uint32_t kb_off = (uint32_t)(((lane >> 4) * 8 + (lane & 7)) * AROW
                                       + (((lane & 15) >> 3) * 16));
    const uint32_t vb_off = (uint32_t)((lane & 15) * AROW + (lane >> 4) * 16);

    for (int kt = 0; kt <= ktmax; kt++) {
        if (kt < ktmax) { CP_WAIT1(); } else { CP_WAIT0(); }
        __syncthreads();

        if (kt == 0) {
            #pragma unroll
            for (int i = 0; i < 2; i++)
                #pragma unroll
                for (int ks = 0; ks < 4; ks++)
                    ldsm4(&qfh[i][ks * 4],
                          sb + a_off + (uint32_t)(i * 16 * AROW) + (uint32_t)(ks * 32));
        }
        int t = kt + 2;
        if (t <= ktmax) {
            att_load_kv(sb + 2 * AQ_BYTES + (uint32_t)(t % 3) * AST,
                        khp, klp, vhp, vlp, t, tid);
            CP_COMMIT();
        }
        const uint32_t kvb = sb + 2 * AQ_BYTES + (uint32_t)(kt % 3) * AST;

        // warp-level causal skip: this warp's rows all precede the tile's keys
        if (kt * 64 > q0 + wid * 32 + 31) continue;

        // ---- scores = Q K^T (3-MMA split) ----
        #pragma unroll
        for (int i = 0; i < 2; i++)
            #pragma unroll
            for (int nc = 0; nc < 8; nc++)
                s[i][nc][0] = s[i][nc][1] = s[i][nc][2] = s[i][nc][3] = 0.f;

        #pragma unroll
        for (int ks = 0; ks < 4; ks++) {
            uint32_t kf[16], kg[16];
            #pragma unroll
            for (int g = 0; g < 4; g++) {
                uint32_t ad = kvb + kb_off + (uint32_t)(g * 16 * AROW) + (uint32_t)(ks * 32);
                ldsm4(kf + g * 4, ad);
                ldsm4(kg + g * 4, ad + AKV_BYTES);
            }
            uint32_t qfl0[4], qfl1[4];
            ldsm4(qfl0, sb + AQ_BYTES + a_off + (uint32_t)(ks * 32));
            ldsm4(qfl1, sb + AQ_BYTES + a_off + 16u * AROW + (uint32_t)(ks * 32));
            #pragma unroll
            for (int nc = 0; nc < 8; nc++) {
                const uint32_t* bh_ = kf + (nc >> 1) * 4 + (nc & 1) * 2;
                const uint32_t* bl_ = kg + (nc >> 1) * 4 + (nc & 1) * 2;
                mma16816(s[0][nc], &qfh[0][ks * 4], bh_);
                mma16816(s[0][nc], qfl0, bh_);
                mma16816(s[0][nc], &qfh[0][ks * 4], bl_);
                mma16816(s[1][nc], &qfh[1][ks * 4], bh_);
                mma16816(s[1][nc], qfl1, bh_);
                mma16816(s[1][nc], &qfh[1][ks * 4], bl_);
            }
        }

        // ---- causal mask (only tiles that straddle the diagonal) ----
        if (kt * 64 + 63 > q0 + wid * 32) {
            const int keyb = kt * 64 + 2 * (lane & 3);
            #pragma unroll
            for (int i = 0; i < 2; i++) {
                const int r0 = q0 + wid * 32 + i * 16 + (lane >> 2);
                #pragma unroll
                for (int nc = 0; nc < 8; nc++) {
                    int k0 = keyb + nc * 8;
                    if (k0     > r0)     s[i][nc][0] = -1e30f;
                    if (k0 + 1 > r0)     s[i][nc][1] = -1e30f;
                    if (k0     > r0 + 8) s[i][nc][2] = -1e30f;
                    if (k0 + 1 > r0 + 8) s[i][nc][3] = -1e30f;
                }
            }
        }

        // ---- online softmax (log2 domain; scores pre-scaled by log2e/8) ----
        #pragma unroll
        for (int i = 0; i < 2; i++) {
            float mx0 = -1e30f, mx1 = -1e30f;
            #pragma unroll
            for (int nc = 0; nc < 8; nc++) {
                mx0 = fmaxf(mx0, fmaxf(s[i][nc][0], s[i][nc][1]));
                mx1 = fmaxf(mx1, fmaxf(s[i][nc][2], s[i][nc][3]));
            }
            mx0 = fmaxf(mx0, __shfl_xor_sync(0xffffffffu, mx0, 1));
            mx0 = fmaxf(mx0, __shfl_xor_sync(0xffffffffu, mx0, 2));
            mx1 = fmaxf(mx1, __shfl_xor_sync(0xffffffffu, mx1, 1));
            mx1 = fmaxf(mx1, __shfl_xor_sync(0xffffffffu, mx1, 2));
            float mn0 = fmaxf(mv[i][0], mx0), mn1 = fmaxf(mv[i][1], mx1);
            float c0 = ex2(mv[i][0] - mn0), c1 = ex2(mv[i][1] - mn1);
            float su0 = 0.f, su1 = 0.f;
            #pragma unroll
            for (int nc = 0; nc < 8; nc++) {
                s[i][nc][0] = ex2(s[i][nc][0] - mn0);
                s[i][nc][1] = ex2(s[i][nc][1] - mn0);
                s[i][nc][2] = ex2(s[i][nc][2] - mn1);
                s[i][nc][3] = ex2(s[i][nc][3] - mn1);
                su0 += s[i][nc][0] + s[i][nc][1];
                su1 += s[i][nc][2] + s[i][nc][3];
            }
            su0 += __shfl_xor_sync(0xffffffffu, su0, 1);
            su0 += __shfl_xor_sync(0xffffffffu, su0, 2);
            su1 += __shfl_xor_sync(0xffffffffu, su1, 1);
            su1 += __shfl_xor_sync(0xffffffffu, su1, 2);
            lv[i][0] = lv[i][0] * c0 + su0;
            lv[i][1] = lv[i][1] * c1 + su1;
            mv[i][0] = mn0; mv[i][1] = mn1;
            #pragma unroll
            for (int nc = 0; nc < 8; nc++) {
                acc[i][nc][0] *= c0; acc[i][nc][1] *= c0;
                acc[i][nc][2] *= c1; acc[i][nc][3] *= c1;
            }
        }

        // ---- ctx += P V (3-MMA split); V frags shared across both A-tiles ----
        #pragma unroll
        for (int ks = 0; ks < 4; ks++) {
            uint32_t vf[16], vg[16];
            #pragma unroll
            for (int g = 0; g < 4; g++) {
                uint32_t ad = kvb + 2 * AKV_BYTES + vb_off
                            + (uint32_t)(ks * 16 * AROW) + (uint32_t)(g * 32);
                ldsm4t(vf + g * 4, ad);
                ldsm4t(vg + g * 4, ad + AKV_BYTES);
            }
            #pragma unroll
            for (int i = 0; i < 2; i++) {
                uint32_t ph[4], pl[4];
                split2(s[i][2 * ks][0],     s[i][2 * ks][1],     ph[0], pl[0]);
                split2(s[i][2 * ks][2],     s[i][2 * ks][3],     ph[1], pl[1]);
                split2(s[i][2 * ks + 1][0], s[i][2 * ks + 1][1], ph[2], pl[2]);
                split2(s[i][2 * ks + 1][2], s[i][2 * ks + 1][3], ph[3], pl[3]);
                #pragma unroll
                for (int nc = 0; nc < 8; nc++) {
                    const uint32_t* bh_ = vf + (nc >> 1) * 4 + (nc & 1) * 2;
                    const uint32_t* bl_ = vg + (nc >> 1) * 4 + (nc & 1) * 2;
                    mma16816(acc[i][nc], ph, bh_);
                    mma16816(acc[i][nc], pl, bh_);
                    mma16816(acc[i][nc], ph, bl_);
                }
            }
        }
    }

    // ---- epilogue: normalize + write ctx hi/lo ----
    const int cb = h * HDIM + 2 * (lane & 3);
    #pragma unroll
    for (int i = 0; i < 2; i++) {
        float i0 = 1.f / lv[i][0], i1 = 1.f / lv[i][1];
        const int r0 = q0 + wid * 32 + i * 16 + (lane >> 2);
        #pragma unroll
        for (int nc = 0; nc < 8; nc++) {
            int cc = cb + nc * 8;
            uint32_t ph, pl;
            split2(acc[i][nc][0] * i0, acc[i][nc][1] * i0, ph, pl);
            size_t off = (size_t)(b * SEQ + r0) * DMODEL + cc;
            *(uint32_t*)(chi + off) = ph;
            *(uint32_t*)(clo + off) = pl;
            split2(acc[i][nc][2] * i1, acc[i][nc][3] * i1, ph, pl);
            off = (size_t)(b * SEQ + r0 + 8) * DMODEL + cc;
            *(uint32_t*)(chi + off) = ph;
            *(uint32_t*)(clo + off) = pl;
        }
    }
}

// ---------------------------------------------------------------------------
extern "C" void kernel_launch(void* const* d_in, const int* in_sizes, int n_in,
                              void* d_out, int out_size)
{
    (void)in_sizes; (void)n_in; (void)out_size;
    const float* x     = (const float*)d_in[0];
    const float* W_qkv = (const float*)d_in[1];
    const float* b_qkv = (const float*)d_in[2];
    const float* W_out = (const float*)d_in[3];
    float* out = (float*)d_out;

    bf *xhi, *xlo, *wqh, *wql, *woh, *wol, *chi, *clo;
    bf *qh, *ql, *kh, *kl, *vh, *vl;
    cudaGetSymbolAddress((void**)&xhi, g_xhi);
    cudaGetSymbolAddress((void**)&xlo, g_xlo);
    cudaGetSymbolAddress((void**)&wqh, g_wqh);
    cudaGetSymbolAddress((void**)&wql, g_wql);
    cudaGetSymbolAddress((void**)&woh, g_woh);
    cudaGetSymbolAddress((void**)&wol, g_wol);
    cudaGetSymbolAddress((void**)&chi, g_chi);
    cudaGetSymbolAddress((void**)&clo, g_clo);
    cudaGetSymbolAddress((void**)&qh, g_qh);
    cudaGetSymbolAddress((void**)&ql, g_ql);
    cudaGetSymbolAddress((void**)&kh, g_kh);
    cudaGetSymbolAddress((void**)&kl, g_kl);
    cudaGetSymbolAddress((void**)&vh, g_vh);
    cudaGetSymbolAddress((void**)&vl, g_vl);

    cudaFuncSetAttribute(gemm_hmma_x3<0>, cudaFuncAttributeMaxDynamicSharedMemorySize,
                         GM_DYN_BYTES);
    cudaFuncSetAttribute(gemm_hmma_x3<1>, cudaFuncAttributeMaxDynamicSharedMemorySize,
                         GM_DYN_BYTES);
    cudaFuncSetAttribute(flash_hmma, cudaFuncAttributeMaxDynamicSharedMemorySize,
                         ATT_SMEM);

    // fused pre-pass (one launch)
    prep_kernel<<<8192, 256>>>(x, W_qkv, W_out, xhi, xlo, wqh, wql, woh, wol);

    gemm_hmma_x3<1><<<dim3(QKV_N / 128, ROWS / 128), 512, GM_DYN_BYTES>>>(
        xhi, xlo, wqh, wql, b_qkv, nullptr,
        qh, ql, kh, kl, vh, vl, ROWS, QKV_N, DMODEL);

    flash_hmma<<<dim3(SEQ / 256, NHEAD, BATCH), 256, ATT_SMEM>>>(
        qh, ql, kh, kl, vh, vl, chi, clo);

    gemm_hmma_x3<0><<<dim3(DMODEL / 128, ROWS / 128), 512, GM_DYN_BYTES>>>(
        chi, clo, woh, wol, nullptr, out,
        nullptr, nullptr, nullptr, nullptr, nullptr, nullptr,
        ROWS, DMODEL, DMODEL);
}

// round 10
// speedup vs baseline: 1.0267x; 1.0267x over previous
#include <cuda_runtime.h>
#include <cuda_bf16.h>
#include <math.h>
#include <stdint.h>

#define BATCH 2
#define SEQ   2048
#define DMODEL 1024
#define NHEAD 16
#define HDIM  64
#define ROWS  (BATCH*SEQ)          // 4096
#define QKV_N (3*DMODEL)           // 3072

typedef __nv_bfloat16 bf;

// ---------------------------------------------------------------------------
// Device scratch
// ---------------------------------------------------------------------------
__device__ bf g_xhi[(size_t)ROWS * DMODEL];
__device__ bf g_xlo[(size_t)ROWS * DMODEL];
__device__ bf g_wqh[(size_t)QKV_N * DMODEL];   // W_qkv^T [3072][1024]
__device__ bf g_wql[(size_t)QKV_N * DMODEL];
__device__ bf g_woh[(size_t)DMODEL * DMODEL];  // W_out^T [1024][1024]
__device__ bf g_wol[(size_t)DMODEL * DMODEL];
__device__ bf g_chi[(size_t)ROWS * DMODEL];    // ctx hi/lo [row][1024]
__device__ bf g_clo[(size_t)ROWS * DMODEL];
// q/k/v split, layout [b][h][s][d]
__device__ bf g_qh[(size_t)BATCH * NHEAD * SEQ * HDIM];
__device__ bf g_ql[(size_t)BATCH * NHEAD * SEQ * HDIM];
__device__ bf g_kh[(size_t)BATCH * NHEAD * SEQ * HDIM];
__device__ bf g_kl[(size_t)BATCH * NHEAD * SEQ * HDIM];
__device__ bf g_vh[(size_t)BATCH * NHEAD * SEQ * HDIM];
__device__ bf g_vl[(size_t)BATCH * NHEAD * SEQ * HDIM];

// ---------------------------------------------------------------------------
// PTX helpers
// ---------------------------------------------------------------------------
__device__ __forceinline__ uint32_t smem_u32(const void* p) {
    uint32_t a;
    asm("{ .reg .u64 t; cvta.to.shared.u64 t, %1; cvt.u32.u64 %0, t; }" : "=r"(a) : "l"(p));
    return a;
}
#define CP16(sm, gm) asm volatile("cp.async.cg.shared.global [%0], [%1], 16;" :: "r"(sm), "l"(gm))
#define CP_COMMIT()  asm volatile("cp.async.commit_group;" ::: "memory")
#define CP_WAIT2()   asm volatile("cp.async.wait_group 2;" ::: "memory")
#define CP_WAIT1()   asm volatile("cp.async.wait_group 1;" ::: "memory")
#define CP_WAIT0()   asm volatile("cp.async.wait_group 0;" ::: "memory")

__device__ __forceinline__ void ldsm4(uint32_t* r, uint32_t addr) {
    asm volatile("ldmatrix.sync.aligned.m8n8.x4.shared.b16 {%0,%1,%2,%3}, [%4];"
                 : "=r"(r[0]), "=r"(r[1]), "=r"(r[2]), "=r"(r[3]) : "r"(addr));
}
__device__ __forceinline__ void ldsm4t(uint32_t* r, uint32_t addr) {
    asm volatile("ldmatrix.sync.aligned.m8n8.x4.trans.shared.b16 {%0,%1,%2,%3}, [%4];"
                 : "=r"(r[0]), "=r"(r[1]), "=r"(r[2]), "=r"(r[3]) : "r"(addr));
}
__device__ __forceinline__ void mma16816(float* c, const uint32_t* a, const uint32_t* b) {
    asm volatile(
        "mma.sync.aligned.m16n8k16.row.col.f32.bf16.bf16.f32 "
        "{%0,%1,%2,%3}, {%4,%5,%6,%7}, {%8,%9}, {%0,%1,%2,%3};"
        : "+f"(c[0]), "+f"(c[1]), "+f"(c[2]), "+f"(c[3])
        : "r"(a[0]), "r"(a[1]), "r"(a[2]), "r"(a[3]), "r"(b[0]), "r"(b[1]));
}
__device__ __forceinline__ float ex2(float x) {
    float y;
    asm("ex2.approx.f32 %0, %1;" : "=f"(y) : "f"(x));
    return y;
}
__device__ __forceinline__ uint32_t packbf(float x, float y) {
    __nv_bfloat162 t = __float22bfloat162_rn(make_float2(x, y));  // x -> low half
    return *(uint32_t*)&t;
}
__device__ __forceinline__ void split2(float x, float y, uint32_t& h, uint32_t& l) {
    h = packbf(x, y);
    float hx = __uint_as_float(h << 16);
    float hy = __uint_as_float(h & 0xffff0000u);
    l = packbf(x - hx, y - hy);
}

// ---------------------------------------------------------------------------
// Fused pre-pass: one launch does x-decomp + both weight transpose-decomps.
// blocks [0,4096)        : x elementwise split (vector4)
// blocks [4096,7168)     : W_qkv^T split (32x32 tiles)
// blocks [7168,8192)     : W_out^T split
// ---------------------------------------------------------------------------
__global__ __launch_bounds__(256) void prep_kernel(
    const float* __restrict__ x, const float* __restrict__ Wq,
    const float* __restrict__ Wo,
    bf* __restrict__ xhi, bf* __restrict__ xlo,
    bf* __restrict__ wqh, bf* __restrict__ wql,
    bf* __restrict__ woh, bf* __restrict__ wol)
{
    __shared__ float t[32][33];
    const int blk = blockIdx.x, tid = threadIdx.x;

    if (blk < 4096) {
        int i = blk * 256 + tid;   // exactly covers ROWS*DMODEL/4
        float4 v = ((const float4*)x)[i];
        uint32_t h0, l0, h1, l1;
        split2(v.x, v.y, h0, l0);
        split2(v.z, v.w, h1, l1);
        *(uint2*)(xhi + 4 * (size_t)i) = make_uint2(h0, h1);
        *(uint2*)(xlo + 4 * (size_t)i) = make_uint2(l0, l1);
        return;
    }

    const float* W; bf *hi, *lo;
    int K, N, bx, by;
    if (blk < 7168) {
        int idx = blk - 4096;           // grid (96, 32)
        W = Wq; hi = wqh; lo = wql; K = DMODEL; N = QKV_N;
        bx = idx % 96; by = idx / 96;
    } else {
        int idx = blk - 7168;           // grid (32, 32)
        W = Wo; hi = woh; lo = wol; K = DMODEL; N = DMODEL;
        bx = idx & 31; by = idx >> 5;
    }
    const int tx = tid & 31, ty = tid >> 5;  // 32 x 8
    const int n0 = bx * 32, k0 = by * 32;
    #pragma unroll
    for (int i = 0; i < 4; i++)
        t[ty + i * 8][tx] = W[(size_t)(k0 + ty + i * 8) * N + n0 + tx];
    __syncthreads();
    #pragma unroll
    for (int i = 0; i < 4; i++) {
        float v = t[tx][ty + i * 8];
        bf h = __float2bfloat16(v);
        bf l = __float2bfloat16(v - __bfloat162float(h));
        size_t o = (size_t)(n0 + ty + i * 8) * K + k0 + tx;
        hi[o] = h; lo[o] = l;
    }
}

// ---------------------------------------------------------------------------
// Tensor-core GEMM via mma.sync, bf16 3-MMA split, fragment-pipelined
// (R6/R8 proven config: 242-254us, tensor 57.5%).
// 512 threads, 16 warps (4x4), warp tile 32x32, BK=32, 4-stage ring, wait2.
// ---------------------------------------------------------------------------
#define GK 32
#define GROW 80
#define GSUB (128 * GROW)
#define GSTAGE (4 * GSUB)     // 40960
#define GNBUF 4
#define GM_DYN_BYTES (GNBUF * GSTAGE + 256)

__device__ __forceinline__ void gm_load_stage(
    uint32_t buf, const bf* gah, const bf* gal, const bf* gbh, const bf* gbl,
    int K, int tid)
{
    int row = tid >> 2, col = tid & 3;
    uint32_t so = (uint32_t)(row * GROW + col * 16);
    size_t g = (size_t)row * K + (size_t)col * 8;
    CP16(buf + so,            gah + g);
    CP16(buf + GSUB + so,     gal + g);
    CP16(buf + 2 * GSUB + so, gbh + g);
    CP16(buf + 3 * GSUB + so, gbl + g);
}

// fr layout: [0..7]=Ah(2 tiles), [8..15]=Al, [16..23]=Bh, [24..31]=Bl
__device__ __forceinline__ void ld_frags(uint32_t* fr, uint32_t sb,
                                         uint32_t a_off, uint32_t b_off, uint32_t ko)
{
    ldsm4(fr + 0,  sb + a_off + ko);
    ldsm4(fr + 4,  sb + a_off + 16u * GROW + ko);
    ldsm4(fr + 8,  sb + GSUB + a_off + ko);
    ldsm4(fr + 12, sb + GSUB + a_off + 16u * GROW + ko);
    ldsm4(fr + 16, sb + 2u * GSUB + b_off + ko);
    ldsm4(fr + 20, sb + 2u * GSUB + b_off + 16u * GROW + ko);
    ldsm4(fr + 24, sb + 3u * GSUB + b_off + ko);
    ldsm4(fr + 28, sb + 3u * GSUB + b_off + 16u * GROW + ko);
}

__device__ __forceinline__ void mma_frags(float acc[2][4][4], const uint32_t* fr)
{
    const uint32_t* ah = fr;
    const uint32_t* al = fr + 8;
    const uint32_t* bh = fr + 16;
    const uint32_t* bl = fr + 24;
    #pragma unroll
    for (int i = 0; i < 2; i++)
        #pragma unroll
        for (int j = 0; j < 4; j++) {
            const uint32_t* bhj = bh + (j >> 1) * 4 + (j & 1) * 2;
            const uint32_t* blj = bl + (j >> 1) * 4 + (j & 1) * 2;
            mma16816(acc[i][j], ah + i * 4, bhj);
            mma16816(acc[i][j], ah + i * 4, blj);
            mma16816(acc[i][j], al + i * 4, bhj);
        }
}

template<int EPI>
__global__ __launch_bounds__(512, 1) void gemm_hmma_x3(
    const bf* __restrict__ Ah, const bf* __restrict__ Al,
    const bf* __restrict__ Bh, const bf* __restrict__ Bl,
    const float* __restrict__ bias, float* __restrict__ C,
    bf* __restrict__ oqh, bf* __restrict__ oql,
    bf* __restrict__ okh, bf* __restrict__ okl,
    bf* __restrict__ ovh, bf* __restrict__ ovl,
    int M, int N, int K)
{
    extern __shared__ __align__(128) char dynsm[];
    const uint32_t smbase = smem_u32(dynsm);

    const int tid = threadIdx.x;
    const int wid = tid >> 5, lane = tid & 31;
    const int wr = wid >> 2, wc = wid & 3;          // warp grid 4 x 4
    const int m0 = blockIdx.y * 128, n0 = blockIdx.x * 128;

    const bf* ah0 = Ah + (size_t)m0 * K;
    const bf* al0 = Al + (size_t)m0 * K;
    const bf* bh0 = Bh + (size_t)n0 * K;
    const bf* bl0 = Bl + (size_t)n0 * K;

    const uint32_t a_off = (uint32_t)((wr * 32 + (lane & 15)) * GROW + (lane >> 4) * 16);
    const uint32_t b_off = (uint32_t)((wc * 32 + (lane >> 4) * 8 + (lane & 7)) * GROW
                                      + (((lane & 15) >> 3) * 16));

    float acc[2][4][4];
    #pragma unroll
    for (int i = 0; i < 2; i++)
        #pragma unroll
        for (int j = 0; j < 4; j++)
            #pragma unroll
            for (int r = 0; r < 4; r++) acc[i][j][r] = 0.f;

    const int NS = K / GK;   // 32

    gm_load_stage(smbase,              ah0,          al0,          bh0,          bl0,          K, tid);
    CP_COMMIT();
    gm_load_stage(smbase + GSTAGE,     ah0 + GK,     al0 + GK,     bh0 + GK,     bl0 + GK,     K, tid);
    CP_COMMIT();
    gm_load_stage(smbase + 2 * GSTAGE, ah0 + 2 * GK, al0 + 2 * GK, bh0 + 2 * GK, bl0 + 2 * GK, K, tid);
    CP_COMMIT();

    for (int s = 0; s < NS; s++) {
        CP_WAIT2();
        __syncthreads();

        const uint32_t sb = smbase + (uint32_t)(s & 3) * GSTAGE;
        uint32_t f0[32], f1[32];
        ld_frags(f0, sb, a_off, b_off, 0);     // kk0 fragments first

        int t = s + 3;                          // then global prefetch
        if (t < NS)
            gm_load_stage(smbase + (uint32_t)(t & 3) * GSTAGE,
                          ah0 + (size_t)t * GK, al0 + (size_t)t * GK,
                          bh0 + (size_t)t * GK, bl0 + (size_t)t * GK, K, tid);
        CP_COMMIT();

        ld_frags(f1, sb, a_off, b_off, 32);    // kk1 fragments before any mma

        mma_frags(acc, f0);
        mma_frags(acc, f1);
    }

    const int er = m0 + wr * 32 + (lane >> 2);
    const int ec = n0 + wc * 32 + 2 * (lane & 3);

    if (EPI == 0) {
        #pragma unroll
        for (int i = 0; i < 2; i++)
            #pragma unroll
            for (int j = 0; j < 4; j++) {
                int r = er + i * 16, c = ec + j * 8;
                *(float2*)(C + (size_t)r * N + c) =
                    make_float2(acc[i][j][0], acc[i][j][1]);
                *(float2*)(C + (size_t)(r + 8) * N + c) =
                    make_float2(acc[i][j][2], acc[i][j][3]);
            }
    } else {
        const int part = ec >> 10;
        bf *dh, *dl;
        if (part == 0)      { dh = oqh; dl = oql; }
        else if (part == 1) { dh = okh; dl = okl; }
        else                { dh = ovh; dl = ovl; }
        // q scale folded in LOG2 domain: 1/sqrt(64) * log2(e)
        const float sc = (part == 0) ? 0.18033688f : 1.0f;
        #pragma unroll
        for (int i = 0; i < 2; i++)
            #pragma unroll
            for (int j = 0; j < 4; j++) {
                int r = er + i * 16, c = ec + j * 8;
                int hh = (c >> 6) & 15, d = c & 63;
                float b0 = bias[c], b1 = bias[c + 1];
                uint32_t ph, pl;
                split2((acc[i][j][0] + b0) * sc, (acc[i][j][1] + b1) * sc, ph, pl);
                size_t off = (((size_t)(r >> 11) * NHEAD + hh) * SEQ + (r & 2047)) * HDIM + d;
                *(uint32_t*)(dh + off) = ph;
                *(uint32_t*)(dl + off) = pl;
                split2((acc[i][j][2] + b0) * sc, (acc[i][j][3] + b1) * sc, ph, pl);
                int r2 = r + 8;
                off = (((size_t)(r2 >> 11) * NHEAD + hh) * SEQ + (r2 & 2047)) * HDIM + d;
                *(uint32_t*)(dh + off) = ph;
                *(uint32_t*)(dl + off) = pl;
            }
    }
}

// ---------------------------------------------------------------------------
// HMMA flash attention (R8 proven config), log2-domain softmax.
// CTA = 128 q rows x one (b,h); 8 warps, warp = 16 q x 64 keys.
// ---------------------------------------------------------------------------
#define AROW 144
#define AQ_BYTES (128 * AROW)
#define AKV_BYTES (64 * AROW)
#define AST (4 * AKV_BYTES)
#define ATT_SMEM (2 * AQ_BYTES + 3 * AST)

__device__ __forceinline__ void att_load_kv(
    uint32_t base, const bf* khp, const bf* klp, const bf* vhp, const bf* vlp,
    int kt, int tid)
{
    #pragma unroll
    for (int i = 0; i < 2; i++) {
        int c = i * 256 + tid;
        int row = c >> 3, col = c & 7;
        uint32_t so = (uint32_t)(row * AROW + col * 16);
        size_t g = (size_t)(kt * 64 + row) * HDIM + col * 8;
        CP16(base + so,                   khp + g);
        CP16(base + AKV_BYTES + so,       klp + g);
        CP16(base + 2 * AKV_BYTES + so,   vhp + g);
        CP16(base + 3 * AKV_BYTES + so,   vlp + g);
    }
}

__device__ __forceinline__ void ld_kfr(uint32_t* f, uint32_t kvb, uint32_t kb_off, int ks)
{
    #pragma unroll
    for (int g = 0; g < 4; g++) {
        uint32_t ad = kvb + kb_off + (uint32_t)(g * 16 * AROW) + (uint32_t)(ks * 32);
        ldsm4(f + g * 4, ad);
        ldsm4(f + 16 + g * 4, ad + AKV_BYTES);
    }
}
__device__ __forceinline__ void ld_vfr(uint32_t* f, uint32_t kvb, uint32_t vb_off, int ks)
{
    #pragma unroll
    for (int g = 0; g < 4; g++) {
        uint32_t ad = kvb + 2 * AKV_BYTES + vb_off
                    + (uint32_t)(ks * 16 * AROW) + (uint32_t)(g * 32);
        ldsm4t(f + g * 4, ad);
        ldsm4t(f + 16 + g * 4, ad + AKV_BYTES);
    }
}

__global__ __launch_bounds__(256) void flash_hmma(
    const bf* __restrict__ qh, const bf* __restrict__ ql,
    const bf* __restrict__ kh, const bf* __restrict__ kl,
    const bf* __restrict__ vh, const bf* __restrict__ vl,
    bf* __restrict__ chi, bf* __restrict__ clo)
{
    extern __shared__ __align__(128) char asmbuf[];
    const uint32_t sb = smem_u32(asmbuf);
    const int tid = threadIdx.x, wid = tid >> 5, lane = tid & 31;
    const int qt = 15 - (int)blockIdx.x;
    const int h = blockIdx.y, b = blockIdx.z;
    const int q0 = qt * 128;
    const int ktmax = 2 * qt + 1;

    const size_t headoff = ((size_t)b * NHEAD + h) * SEQ * HDIM;
    const bf* qhp = qh + headoff + (size_t)q0 * HDIM;
    const bf* qlp = ql + headoff + (size_t)q0 * HDIM;
    const bf* khp = kh + headoff;
    const bf* klp = kl + headoff;
    const bf* vhp = vh + headoff;
    const bf* vlp = vl + headoff;

    #pragma unroll
    for (int i = 0; i < 4; i++) {
        int c = i * 256 + tid;
        int row = c >> 3, col = c & 7;
        uint32_t so = (uint32_t)(row * AROW + col * 16);
        size_t g = (size_t)row * HDIM + col * 8;
        CP16(sb + so,            qhp + g);
        CP16(sb + AQ_BYTES + so, qlp + g);
    }
    att_load_kv(sb + 2 * AQ_BYTES, khp, klp, vhp, vlp, 0, tid);
    CP_COMMIT();
    att_load_kv(sb + 2 * AQ_BYTES + AST, khp, klp, vhp, vlp, 1, tid);
    CP_COMMIT();

    float s[8][4], acc[8][4];
    float m0v = -1e30f, m1v = -1e30f, l0v = 0.f, l1v = 0.f;
    #pragma unroll
    for (int nc = 0; nc < 8; nc++) {
        acc[nc][0] = acc[nc][1] = acc[nc][2] = acc[nc][3] = 0.f;
    }
    uint32_t qfh[16], qfl[16];

    const uint32_t a_off = (uint32_t)((wid * 16 + (lane & 15)) * AROW + (lane >> 4) * 16);
    const uint32_t kb_off = (uint32_t)(((lane >> 4) * 8 + (lane & 7)) * AROW
                                       + (((lane & 15) >> 3) * 16));
    const uint32_t vb_off = (uint32_t)((lane & 15) * AROW + (lane >> 4) * 16);

    for (int kt = 0; kt <= ktmax; kt++) {
        if (kt < ktmax) { CP_WAIT1(); } else { CP_WAIT0(); }
        __syncthreads();

        if (kt == 0) {
            #pragma unroll
            for (int ks = 0; ks < 4; ks++) {
                ldsm4(&qfh[ks * 4], sb + a_off + (uint32_t)(ks * 32));
                ldsm4(&qfl[ks * 4], sb + AQ_BYTES + a_off + (uint32_t)(ks * 32));
            }
        }
        int t = kt + 2;
        if (t <= ktmax) {
            att_load_kv(sb + 2 * AQ_BYTES + (uint32_t)(t % 3) * AST,
                        khp, klp, vhp, vlp, t, tid);
            CP_COMMIT();
        }
        const uint32_t kvb = sb + 2 * AQ_BYTES + (uint32_t)(kt % 3) * AST;

        // ---- scores = Q K^T (3-MMA split), K-fragments double-buffered ----
        #pragma unroll
        for (int nc = 0; nc < 8; nc++) {
            s[nc][0] = s[nc][1] = s[nc][2] = s[nc][3] = 0.f;
        }
        {
            uint32_t kfb[2][32];
            ld_kfr(kfb[0], kvb, kb_off, 0);
            #pragma unroll
            for (int ks = 0; ks < 4; ks++) {
                if (ks < 3) ld_kfr(kfb[(ks + 1) & 1], kvb, kb_off, ks + 1);
                const uint32_t* kf = kfb[ks & 1];
                const uint32_t* kg = kf + 16;
                #pragma unroll
                for (int nc = 0; nc < 8; nc++) {
                    const uint32_t* bh_ = kf + (nc >> 1) * 4 + (nc & 1) * 2;
                    const uint32_t* bl_ = kg + (nc >> 1) * 4 + (nc & 1) * 2;
                    mma16816(s[nc], &qfh[ks * 4], bh_);
                    mma16816(s[nc], &qfl[ks * 4], bh_);
                    mma16816(s[nc], &qfh[ks * 4], bl_);
                }
            }
        }

        // ---- online softmax (log2 domain; scores pre-scaled by log2e/8) ----
        if (kt >= 2 * qt) {
            const int keyb = kt * 64 + 2 * (lane & 3);
            const int r0 = q0 + wid * 16 + (lane >> 2);
            #pragma unroll
            for (int nc = 0; nc < 8; nc++) {
                int k0 = keyb + nc * 8;
                if (k0     > r0)     s[nc][0] = -1e30f;
                if (k0 + 1 > r0)     s[nc][1] = -1e30f;
                if (k0     > r0 + 8) s[nc][2] = -1e30f;
                if (k0 + 1 > r0 + 8) s[nc][3] = -1e30f;
            }
        }
        float mx0 = -1e30f, mx1 = -1e30f;
        #pragma unroll
        for (int nc = 0; nc < 8; nc++) {
            mx0 = fmaxf(mx0, fmaxf(s[nc][0], s[nc][1]));
            mx1 = fmaxf(mx1, fmaxf(s[nc][2], s[nc][3]));
        }
        mx0 = fmaxf(mx0, __shfl_xor_sync(0xffffffffu, mx0, 1));
        mx0 = fmaxf(mx0, __shfl_xor_sync(0xffffffffu, mx0, 2));
        mx1 = fmaxf(mx1, __shfl_xor_sync(0xffffffffu, mx1, 1));
        mx1 = fmaxf(mx1, __shfl_xor_sync(0xffffffffu, mx1, 2));
        float mn0 = fmaxf(m0v, mx0), mn1 = fmaxf(m1v, mx1);
        float c0 = ex2(m0v - mn0), c1 = ex2(m1v - mn1);
        float su0 = 0.f, su1 = 0.f;
        #pragma unroll
        for (int nc = 0; nc < 8; nc++) {
            s[nc][0] = ex2(s[nc][0] - mn0);
            s[nc][1] = ex2(s[nc][1] - mn0);
            s[nc][2] = ex2(s[nc][2] - mn1);
            s[nc][3] = ex2(s[nc][3] - mn1);
            su0 += s[nc][0] + s[nc][1];
            su1 += s[nc][2] + s[nc][3];
        }
        su0 += __shfl_xor_sync(0xffffffffu, su0, 1);
        su0 += __shfl_xor_sync(0xffffffffu, su0, 2);
        su1 += __shfl_xor_sync(0xffffffffu, su1, 1);
        su1 += __shfl_xor_sync(0xffffffffu, su1, 2);
        l0v = l0v * c0 + su0;
        l1v = l1v * c1 + su1;
        m0v = mn0; m1v = mn1;
        #pragma unroll
        for (int nc = 0; nc < 8; nc++) {
            acc[nc][0] *= c0; acc[nc][1] *= c0;
            acc[nc][2] *= c1; acc[nc][3] *= c1;
        }

        // ---- ctx += P V (3-MMA split), V-fragments double-buffered ----
        {
            uint32_t vfb[2][32];
            ld_vfr(vfb[0], kvb, vb_off, 0);
            #pragma unroll
            for (int ks = 0; ks < 4; ks++) {
                if (ks < 3) ld_vfr(vfb[(ks + 1) & 1], kvb, vb_off, ks + 1);
                uint32_t ph[4], pl[4];
                split2(s[2 * ks][0],     s[2 * ks][1],     ph[0], pl[0]);
                split2(s[2 * ks][2],     s[2 * ks][3],     ph[1], pl[1]);
                split2(s[2 * ks + 1][0], s[2 * ks + 1][1], ph[2], pl[2]);
                split2(s[2 * ks + 1][2], s[2 * ks + 1][3], ph[3], pl[3]);
                const uint32_t* vf = vfb[ks & 1];
                const uint32_t* vg = vf + 16;
                #pragma unroll
                for (int nc = 0; nc < 8; nc++) {
                    const uint32_t* bh_ = vf + (nc >> 1) * 4 + (nc & 1) * 2;
                    const uint32_t* bl_ = vg + (nc >> 1) * 4 + (nc & 1) * 2;
                    mma16816(acc[nc], ph, bh_);
                    mma16816(acc[nc], pl, bh_);
                    mma16816(acc[nc], ph, bl_);
                }
            }
        }
    }

    float i0 = 1.f / l0v, i1 = 1.f / l1v;
    const int r0 = q0 + wid * 16 + (lane >> 2);
    const int cb = h * HDIM + 2 * (lane & 3);
    #pragma unroll
    for (int nc = 0; nc < 8; nc++) {
        int cc = cb + nc * 8;
        uint32_t ph, pl;
        split2(acc[nc][0] * i0, acc[nc][1] * i0, ph, pl);
        size_t off = (size_t)(b * SEQ + r0) * DMODEL + cc;
        *(uint32_t*)(chi + off) = ph;
        *(uint32_t*)(clo + off) = pl;
        split2(acc[nc][2] * i1, acc[nc][3] * i1, ph, pl);
        off = (size_t)(b * SEQ + r0 + 8) * DMODEL + cc;
        *(uint32_t*)(chi + off) = ph;
        *(uint32_t*)(clo + off) = pl;
    }
}

// ---------------------------------------------------------------------------
extern "C" void kernel_launch(void* const* d_in, const int* in_sizes, int n_in,
                              void* d_out, int out_size)
{
    (void)in_sizes; (void)n_in; (void)out_size;
    const float* x     = (const float*)d_in[0];
    const float* W_qkv = (const float*)d_in[1];
    const float* b_qkv = (const float*)d_in[2];
    const float* W_out = (const float*)d_in[3];
    float* out = (float*)d_out;

    bf *xhi, *xlo, *wqh, *wql, *woh, *wol, *chi, *clo;
    bf *qh, *ql, *kh, *kl, *vh, *vl;
    cudaGetSymbolAddress((void**)&xhi, g_xhi);
    cudaGetSymbolAddress((void**)&xlo, g_xlo);
    cudaGetSymbolAddress((void**)&wqh, g_wqh);
    cudaGetSymbolAddress((void**)&wql, g_wql);
    cudaGetSymbolAddress((void**)&woh, g_woh);
    cudaGetSymbolAddress((void**)&wol, g_wol);
    cudaGetSymbolAddress((void**)&chi, g_chi);
    cudaGetSymbolAddress((void**)&clo, g_clo);
    cudaGetSymbolAddress((void**)&qh, g_qh);
    cudaGetSymbolAddress((void**)&ql, g_ql);
    cudaGetSymbolAddress((void**)&kh, g_kh);
    cudaGetSymbolAddress((void**)&kl, g_kl);
    cudaGetSymbolAddress((void**)&vh, g_vh);
    cudaGetSymbolAddress((void**)&vl, g_vl);

    cudaFuncSetAttribute(gemm_hmma_x3<0>, cudaFuncAttributeMaxDynamicSharedMemorySize,
                         GM_DYN_BYTES);
    cudaFuncSetAttribute(gemm_hmma_x3<1>, cudaFuncAttributeMaxDynamicSharedMemorySize,
                         GM_DYN_BYTES);
    cudaFuncSetAttribute(flash_hmma, cudaFuncAttributeMaxDynamicSharedMemorySize,
                         ATT_SMEM);

    // fused pre-pass (one launch)
    prep_kernel<<<8192, 256>>>(x, W_qkv, W_out, xhi, xlo, wqh, wql, woh, wol);

    gemm_hmma_x3<1><<<dim3(QKV_N / 128, ROWS / 128), 512, GM_DYN_BYTES>>>(
        xhi, xlo, wqh, wql, b_qkv, nullptr,
        qh, ql, kh, kl, vh, vl, ROWS, QKV_N, DMODEL);

    flash_hmma<<<dim3(16, NHEAD, BATCH), 256, ATT_SMEM>>>(
        qh, ql, kh, kl, vh, vl, chi, clo);

    gemm_hmma_x3<0><<<dim3(DMODEL / 128, ROWS / 128), 512, GM_DYN_BYTES>>>(
        chi, clo, woh, wol, nullptr, out,
        nullptr, nullptr, nullptr, nullptr, nullptr, nullptr,
        ROWS, DMODEL, DMODEL);
}

// round 11
// speedup vs baseline: 1.0300x; 1.0032x over previous
#include <cuda_runtime.h>
#include <cuda_bf16.h>
#include <math.h>
#include <stdint.h>

#define BATCH 2
#define SEQ   2048
#define DMODEL 1024
#define NHEAD 16
#define HDIM  64
#define ROWS  (BATCH*SEQ)          // 4096
#define QKV_N (3*DMODEL)           // 3072

typedef __nv_bfloat16 bf;

// ---------------------------------------------------------------------------
// Device scratch
// ---------------------------------------------------------------------------
__device__ bf g_xhi[(size_t)ROWS * DMODEL];
__device__ bf g_xlo[(size_t)ROWS * DMODEL];
__device__ bf g_wqh[(size_t)QKV_N * DMODEL];   // W_qkv^T [3072][1024]
__device__ bf g_wql[(size_t)QKV_N * DMODEL];
__device__ bf g_woh[(size_t)DMODEL * DMODEL];  // W_out^T [1024][1024]
__device__ bf g_wol[(size_t)DMODEL * DMODEL];
__device__ bf g_chi[(size_t)ROWS * DMODEL];    // ctx hi/lo [row][1024]
__device__ bf g_clo[(size_t)ROWS * DMODEL];
// q/k/v split, layout [b][h][s][d]
__device__ bf g_qh[(size_t)BATCH * NHEAD * SEQ * HDIM];
__device__ bf g_ql[(size_t)BATCH * NHEAD * SEQ * HDIM];
__device__ bf g_kh[(size_t)BATCH * NHEAD * SEQ * HDIM];
__device__ bf g_kl[(size_t)BATCH * NHEAD * SEQ * HDIM];
__device__ bf g_vh[(size_t)BATCH * NHEAD * SEQ * HDIM];
__device__ bf g_vl[(size_t)BATCH * NHEAD * SEQ * HDIM];

// ---------------------------------------------------------------------------
// PTX helpers
// ---------------------------------------------------------------------------
__device__ __forceinline__ uint32_t smem_u32(const void* p) {
    uint32_t a;
    asm("{ .reg .u64 t; cvta.to.shared.u64 t, %1; cvt.u32.u64 %0, t; }" : "=r"(a) : "l"(p));
    return a;
}
#define CP16(sm, gm) asm volatile("cp.async.cg.shared.global [%0], [%1], 16;" :: "r"(sm), "l"(gm))
#define CP_COMMIT()  asm volatile("cp.async.commit_group;" ::: "memory")
#define CP_WAIT2()   asm volatile("cp.async.wait_group 2;" ::: "memory")
#define CP_WAIT1()   asm volatile("cp.async.wait_group 1;" ::: "memory")
#define CP_WAIT0()   asm volatile("cp.async.wait_group 0;" ::: "memory")

__device__ __forceinline__ void ldsm4(uint32_t* r, uint32_t addr) {
    asm volatile("ldmatrix.sync.aligned.m8n8.x4.shared.b16 {%0,%1,%2,%3}, [%4];"
                 : "=r"(r[0]), "=r"(r[1]), "=r"(r[2]), "=r"(r[3]) : "r"(addr));
}
__device__ __forceinline__ void ldsm4t(uint32_t* r, uint32_t addr) {
    asm volatile("ldmatrix.sync.aligned.m8n8.x4.trans.shared.b16 {%0,%1,%2,%3}, [%4];"
                 : "=r"(r[0]), "=r"(r[1]), "=r"(r[2]), "=r"(r[3]) : "r"(addr));
}
__device__ __forceinline__ void mma16816(float* c, const uint32_t* a, const uint32_t* b) {
    asm volatile(
        "mma.sync.aligned.m16n8k16.row.col.f32.bf16.bf16.f32 "
        "{%0,%1,%2,%3}, {%4,%5,%6,%7}, {%8,%9}, {%0,%1,%2,%3};"
        : "+f"(c[0]), "+f"(c[1]), "+f"(c[2]), "+f"(c[3])
        : "r"(a[0]), "r"(a[1]), "r"(a[2]), "r"(a[3]), "r"(b[0]), "r"(b[1]));
}
__device__ __forceinline__ float ex2(float x) {
    float y;
    asm("ex2.approx.f32 %0, %1;" : "=f"(y) : "f"(x));
    return y;
}
__device__ __forceinline__ uint32_t packbf(float x, float y) {
    __nv_bfloat162 t = __float22bfloat162_rn(make_float2(x, y));  // x -> low half
    return *(uint32_t*)&t;
}
__device__ __forceinline__ void split2(float x, float y, uint32_t& h, uint32_t& l) {
    h = packbf(x, y);
    float hx = __uint_as_float(h << 16);
    float hy = __uint_as_float(h & 0xffff0000u);
    l = packbf(x - hx, y - hy);
}

// ---------------------------------------------------------------------------
// Fused pre-pass: one launch does x-decomp + both weight transpose-decomps.
// ---------------------------------------------------------------------------
__global__ __launch_bounds__(256) void prep_kernel(
    const float* __restrict__ x, const float* __restrict__ Wq,
    const float* __restrict__ Wo,
    bf* __restrict__ xhi, bf* __restrict__ xlo,
    bf* __restrict__ wqh, bf* __restrict__ wql,
    bf* __restrict__ woh, bf* __restrict__ wol)
{
    __shared__ float t[32][33];
    const int blk = blockIdx.x, tid = threadIdx.x;

    if (blk < 4096) {
        int i = blk * 256 + tid;   // exactly covers ROWS*DMODEL/4
        float4 v = ((const float4*)x)[i];
        uint32_t h0, l0, h1, l1;
        split2(v.x, v.y, h0, l0);
        split2(v.z, v.w, h1, l1);
        *(uint2*)(xhi + 4 * (size_t)i) = make_uint2(h0, h1);
        *(uint2*)(xlo + 4 * (size_t)i) = make_uint2(l0, l1);
        return;
    }

    const float* W; bf *hi, *lo;
    int K, N, bx, by;
    if (blk < 7168) {
        int idx = blk - 4096;           // grid (96, 32)
        W = Wq; hi = wqh; lo = wql; K = DMODEL; N = QKV_N;
        bx = idx % 96; by = idx / 96;
    } else {
        int idx = blk - 7168;           // grid (32, 32)
        W = Wo; hi = woh; lo = wol; K = DMODEL; N = DMODEL;
        bx = idx & 31; by = idx >> 5;
    }
    const int tx = tid & 31, ty = tid >> 5;  // 32 x 8
    const int n0 = bx * 32, k0 = by * 32;
    #pragma unroll
    for (int i = 0; i < 4; i++)
        t[ty + i * 8][tx] = W[(size_t)(k0 + ty + i * 8) * N + n0 + tx];
    __syncthreads();
    #pragma unroll
    for (int i = 0; i < 4; i++) {
        float v = t[tx][ty + i * 8];
        bf h = __float2bfloat16(v);
        bf l = __float2bfloat16(v - __bfloat162float(h));
        size_t o = (size_t)(n0 + ty + i * 8) * K + k0 + tx;
        hi[o] = h; lo[o] = l;
    }
}

// ---------------------------------------------------------------------------
// Tensor-core GEMM via mma.sync, bf16 3-MMA split, fragment-pipelined.
// R11: MMAs reordered term-major (same-acc reuse distance 1 -> 8).
// 512 threads, 16 warps (4x4), warp tile 32x32, BK=32, 4-stage ring, wait2.
// ---------------------------------------------------------------------------
#define GK 32
#define GROW 80
#define GSUB (128 * GROW)
#define GSTAGE (4 * GSUB)     // 40960
#define GNBUF 4
#define GM_DYN_BYTES (GNBUF * GSTAGE + 256)

__device__ __forceinline__ void gm_load_stage(
    uint32_t buf, const bf* gah, const bf* gal, const bf* gbh, const bf* gbl,
    int K, int tid)
{
    int row = tid >> 2, col = tid & 3;
    uint32_t so = (uint32_t)(row * GROW + col * 16);
    size_t g = (size_t)row * K + (size_t)col * 8;
    CP16(buf + so,            gah + g);
    CP16(buf + GSUB + so,     gal + g);
    CP16(buf + 2 * GSUB + so, gbh + g);
    CP16(buf + 3 * GSUB + so, gbl + g);
}

// fr layout: [0..7]=Ah(2 tiles), [8..15]=Al, [16..23]=Bh, [24..31]=Bl
__device__ __forceinline__ void ld_frags(uint32_t* fr, uint32_t sb,
                                         uint32_t a_off, uint32_t b_off, uint32_t ko)
{
    ldsm4(fr + 0,  sb + a_off + ko);
    ldsm4(fr + 4,  sb + a_off + 16u * GROW + ko);
    ldsm4(fr + 8,  sb + GSUB + a_off + ko);
    ldsm4(fr + 12, sb + GSUB + a_off + 16u * GROW + ko);
    ldsm4(fr + 16, sb + 2u * GSUB + b_off + ko);
    ldsm4(fr + 20, sb + 2u * GSUB + b_off + 16u * GROW + ko);
    ldsm4(fr + 24, sb + 3u * GSUB + b_off + ko);
    ldsm4(fr + 28, sb + 3u * GSUB + b_off + 16u * GROW + ko);
}

// Term-major: all Ah*Bh (8 distinct accs), then Ah*Bl, then Al*Bh.
__device__ __forceinline__ void mma_frags(float acc[2][4][4], const uint32_t* fr)
{
    const uint32_t* ah = fr;
    const uint32_t* al = fr + 8;
    const uint32_t* bh = fr + 16;
    const uint32_t* bl = fr + 24;
    #pragma unroll
    for (int i = 0; i < 2; i++)
        #pragma unroll
        for (int j = 0; j < 4; j++)
            mma16816(acc[i][j], ah + i * 4, bh + (j >> 1) * 4 + (j & 1) * 2);
    #pragma unroll
    for (int i = 0; i < 2; i++)
        #pragma unroll
        for (int j = 0; j < 4; j++)
            mma16816(acc[i][j], ah + i * 4, bl + (j >> 1) * 4 + (j & 1) * 2);
    #pragma unroll
    for (int i = 0; i < 2; i++)
        #pragma unroll
        for (int j = 0; j < 4; j++)
            mma16816(acc[i][j], al + i * 4, bh + (j >> 1) * 4 + (j & 1) * 2);
}

template<int EPI>
__global__ __launch_bounds__(512, 1) void gemm_hmma_x3(
    const bf* __restrict__ Ah, const bf* __restrict__ Al,
    const bf* __restrict__ Bh, const bf* __restrict__ Bl,
    const float* __restrict__ bias, float* __restrict__ C,
    bf* __restrict__ oqh, bf* __restrict__ oql,
    bf* __restrict__ okh, bf* __restrict__ okl,
    bf* __restrict__ ovh, bf* __restrict__ ovl,
    int M, int N, int K)
{
    extern __shared__ __align__(128) char dynsm[];
    const uint32_t smbase = smem_u32(dynsm);

    const int tid = threadIdx.x;
    const int wid = tid >> 5, lane = tid & 31;
    const int wr = wid >> 2, wc = wid & 3;          // warp grid 4 x 4
    const int m0 = blockIdx.y * 128, n0 = blockIdx.x * 128;

    const bf* ah0 = Ah + (size_t)m0 * K;
    const bf* al0 = Al + (size_t)m0 * K;
    const bf* bh0 = Bh + (size_t)n0 * K;
    const bf* bl0 = Bl + (size_t)n0 * K;

    const uint32_t a_off = (uint32_t)((wr * 32 + (lane & 15)) * GROW + (lane >> 4) * 16);
    const uint32_t b_off = (uint32_t)((wc * 32 + (lane >> 4) * 8 + (lane & 7)) * GROW
                                      + (((lane & 15) >> 3) * 16));

    float acc[2][4][4];
    #pragma unroll
    for (int i = 0; i < 2; i++)
        #pragma unroll
        for (int j = 0; j < 4; j++)
            #pragma unroll
            for (int r = 0; r < 4; r++) acc[i][j][r] = 0.f;

    const int NS = K / GK;   // 32

    gm_load_stage(smbase,              ah0,          al0,          bh0,          bl0,          K, tid);
    CP_COMMIT();
    gm_load_stage(smbase + GSTAGE,     ah0 + GK,     al0 + GK,     bh0 + GK,     bl0 + GK,     K, tid);
    CP_COMMIT();
    gm_load_stage(smbase + 2 * GSTAGE, ah0 + 2 * GK, al0 + 2 * GK, bh0 + 2 * GK, bl0 + 2 * GK, K, tid);
    CP_COMMIT();

    for (int s = 0; s < NS; s++) {
        CP_WAIT2();
        __syncthreads();

        const uint32_t sb = smbase + (uint32_t)(s & 3) * GSTAGE;
        uint32_t f0[32], f1[32];
        ld_frags(f0, sb, a_off, b_off, 0);     // kk0 fragments first

        int t = s + 3;                          // then global prefetch
        if (t < NS)
            gm_load_stage(smbase + (uint32_t)(t & 3) * GSTAGE,
                          ah0 + (size_t)t * GK, al0 + (size_t)t * GK,
                          bh0 + (size_t)t * GK, bl0 + (size_t)t * GK, K, tid);
        CP_COMMIT();

        ld_frags(f1, sb, a_off, b_off, 32);    // kk1 fragments before any mma

        mma_frags(acc, f0);
        mma_frags(acc, f1);
    }

    const int er = m0 + wr * 32 + (lane >> 2);
    const int ec = n0 + wc * 32 + 2 * (lane & 3);

    if (EPI == 0) {
        #pragma unroll
        for (int i = 0; i < 2; i++)
            #pragma unroll
            for (int j = 0; j < 4; j++) {
                int r = er + i * 16, c = ec + j * 8;
                *(float2*)(C + (size_t)r * N + c) =
                    make_float2(acc[i][j][0], acc[i][j][1]);
                *(float2*)(C + (size_t)(r + 8) * N + c) =
                    make_float2(acc[i][j][2], acc[i][j][3]);
            }
    } else {
        const int part = ec >> 10;
        bf *dh, *dl;
        if (part == 0)      { dh = oqh; dl = oql; }
        else if (part == 1) { dh = okh; dl = okl; }
        else                { dh = ovh; dl = ovl; }
        // q scale folded in LOG2 domain: 1/sqrt(64) * log2(e)
        const float sc = (part == 0) ? 0.18033688f : 1.0f;
        #pragma unroll
        for (int i = 0; i < 2; i++)
            #pragma unroll
            for (int j = 0; j < 4; j++) {
                int r = er + i * 16, c = ec + j * 8;
                int hh = (c >> 6) & 15, d = c & 63;
                float b0 = bias[c], b1 = bias[c + 1];
                uint32_t ph, pl;
                split2((acc[i][j][0] + b0) * sc, (acc[i][j][1] + b1) * sc, ph, pl);
                size_t off = (((size_t)(r >> 11) * NHEAD + hh) * SEQ + (r & 2047)) * HDIM + d;
                *(uint32_t*)(dh + off) = ph;
                *(uint32_t*)(dl + off) = pl;
                split2((acc[i][j][2] + b0) * sc, (acc[i][j][3] + b1) * sc, ph, pl);
                int r2 = r + 8;
                off = (((size_t)(r2 >> 11) * NHEAD + hh) * SEQ + (r2 & 2047)) * HDIM + d;
                *(uint32_t*)(dh + off) = ph;
                *(uint32_t*)(dl + off) = pl;
            }
    }
}

// ---------------------------------------------------------------------------
// HMMA flash attention, log2-domain softmax; MMAs term-major (R11 reorder).
// CTA = 128 q rows x one (b,h); 8 warps, warp = 16 q x 64 keys.
// ---------------------------------------------------------------------------
#define AROW 144
#define AQ_BYTES (128 * AROW)
#define AKV_BYTES (64 * AROW)
#define AST (4 * AKV_BYTES)
#define ATT_SMEM (2 * AQ_BYTES + 3 * AST)

__device__ __forceinline__ void att_load_kv(
    uint32_t base, const bf* khp, const bf* klp, const bf* vhp, const bf* vlp,
    int kt, int tid)
{
    #pragma unroll
    for (int i = 0; i < 2; i++) {
        int c = i * 256 + tid;
        int row = c >> 3, col = c & 7;
        uint32_t so = (uint32_t)(row * AROW + col * 16);
        size_t g = (size_t)(kt * 64 + row) * HDIM + col * 8;
        CP16(base + so,                   khp + g);
        CP16(base + AKV_BYTES + so,       klp + g);
        CP16(base + 2 * AKV_BYTES + so,   vhp + g);
        CP16(base + 3 * AKV_BYTES + so,   vlp + g);
    }
}

__device__ __forceinline__ void ld_kfr(uint32_t* f, uint32_t kvb, uint32_t kb_off, int ks)
{
    #pragma unroll
    for (int g = 0; g < 4; g++) {
        uint32_t ad = kvb + kb_off + (uint32_t)(g * 16 * AROW) + (uint32_t)(ks * 32);
        ldsm4(f + g * 4, ad);
        ldsm4(f + 16 + g * 4, ad + AKV_BYTES);
    }
}
__device__ __forceinline__ void ld_vfr(uint32_t* f, uint32_t kvb, uint32_t vb_off, int ks)
{
    #pragma unroll
    for (int g = 0; g < 4; g++) {
        uint32_t ad = kvb + 2 * AKV_BYTES + vb_off
                    + (uint32_t)(ks * 16 * AROW) + (uint32_t)(g * 32);
        ldsm4t(f + g * 4, ad);
        ldsm4t(f + 16 + g * 4, ad + AKV_BYTES);
    }
}

__global__ __launch_bounds__(256) void flash_hmma(
    const bf* __restrict__ qh, const bf* __restrict__ ql,
    const bf* __restrict__ kh, const bf* __restrict__ kl,
    const bf* __restrict__ vh, const bf* __restrict__ vl,
    bf* __restrict__ chi, bf* __restrict__ clo)
{
    extern __shared__ __align__(128) char asmbuf[];
    const uint32_t sb = smem_u32(asmbuf);
    const int tid = threadIdx.x, wid = tid >> 5, lane = tid & 31;
    const int qt = 15 - (int)blockIdx.x;
    const int h = blockIdx.y, b = blockIdx.z;
    const int q0 = qt * 128;
    const int ktmax = 2 * qt + 1;

    const size_t headoff = ((size_t)b * NHEAD + h) * SEQ * HDIM;
    const bf* qhp = qh + headoff + (size_t)q0 * HDIM;
    const bf* qlp = ql + headoff + (size_t)q0 * HDIM;
    const bf* khp = kh + headoff;
    const bf* klp = kl + headoff;
    const bf* vhp = vh + headoff;
    const bf* vlp = vl + headoff;

    #pragma unroll
    for (int i = 0; i < 4; i++) {
        int c = i * 256 + tid;
        int row = c >> 3, col = c & 7;
        uint32_t so = (uint32_t)(row * AROW + col * 16);
        size_t g = (size_t)row * HDIM + col * 8;
        CP16(sb + so,            qhp + g);
        CP16(sb + AQ_BYTES + so, qlp + g);
    }
    att_load_kv(sb + 2 * AQ_BYTES, khp, klp, vhp, vlp, 0, tid);
    CP_COMMIT();
    att_load_kv(sb + 2 * AQ_BYTES + AST, khp, klp, vhp, vlp, 1, tid);
    CP_COMMIT();

    float s[8][4], acc[8][4];
    float m0v = -1e30f, m1v = -1e30f, l0v = 0.f, l1v = 0.f;
    #pragma unroll
    for (int nc = 0; nc < 8; nc++) {
        acc[nc][0] = acc[nc][1] = acc[nc][2] = acc[nc][3] = 0.f;
    }
    uint32_t qfh[16], qfl[16];

    const uint32_t a_off = (uint32_t)((wid * 16 + (lane & 15)) * AROW + (lane >> 4) * 16);
    const uint32_t kb_off = (uint32_t)(((lane >> 4) * 8 + (lane & 7)) * AROW
                                       + (((lane & 15) >> 3) * 16));
    const uint32_t vb_off = (uint32_t)((lane & 15) * AROW + (lane >> 4) * 16);

    for (int kt = 0; kt <= ktmax; kt++) {
        if (kt < ktmax) { CP_WAIT1(); } else { CP_WAIT0(); }
        __syncthreads();

        if (kt == 0) {
            #pragma unroll
            for (int ks = 0; ks < 4; ks++) {
                ldsm4(&qfh[ks * 4], sb + a_off + (uint32_t)(ks * 32));
                ldsm4(&qfl[ks * 4], sb + AQ_BYTES + a_off + (uint32_t)(ks * 32));
            }
        }
        int t = kt + 2;
        if (t <= ktmax) {
            att_load_kv(sb + 2 * AQ_BYTES + (uint32_t)(t % 3) * AST,
                        khp, klp, vhp, vlp, t, tid);
            CP_COMMIT();
        }
        const uint32_t kvb = sb + 2 * AQ_BYTES + (uint32_t)(kt % 3) * AST;

        // ---- scores = Q K^T (3-MMA split), term-major issue order ----
        #pragma unroll
        for (int nc = 0; nc < 8; nc++) {
            s[nc][0] = s[nc][1] = s[nc][2] = s[nc][3] = 0.f;
        }
        {
            uint32_t kfb[2][32];
            ld_kfr(kfb[0], kvb, kb_off, 0);
            #pragma unroll
            for (int ks = 0; ks < 4; ks++) {
                if (ks < 3) ld_kfr(kfb[(ks + 1) & 1], kvb, kb_off, ks + 1);
                const uint32_t* kf = kfb[ks & 1];
                const uint32_t* kg = kf + 16;
                #pragma unroll
                for (int nc = 0; nc < 8; nc++)
                    mma16816(s[nc], &qfh[ks * 4], kf + (nc >> 1) * 4 + (nc & 1) * 2);
                #pragma unroll
                for (int nc = 0; nc < 8; nc++)
                    mma16816(s[nc], &qfl[ks * 4], kf + (nc >> 1) * 4 + (nc & 1) * 2);
                #pragma unroll
                for (int nc = 0; nc < 8; nc++)
                    mma16816(s[nc], &qfh[ks * 4], kg + (nc >> 1) * 4 + (nc & 1) * 2);
            }
        }

        // ---- online softmax (log2 domain; scores pre-scaled by log2e/8) ----
        if (kt >= 2 * qt) {
            const int keyb = kt * 64 + 2 * (lane & 3);
            const int r0 = q0 + wid * 16 + (lane >> 2);
            #pragma unroll
            for (int nc = 0; nc < 8; nc++) {
                int k0 = keyb + nc * 8;
                if (k0     > r0)     s[nc][0] = -1e30f;
                if (k0 + 1 > r0)     s[nc][1] = -1e30f;
                if (k0     > r0 + 8) s[nc][2] = -1e30f;
                if (k0 + 1 > r0 + 8) s[nc][3] = -1e30f;
            }
        }
        float mx0 = -1e30f, mx1 = -1e30f;
        #pragma unroll
        for (int nc = 0; nc < 8; nc++) {
            mx0 = fmaxf(mx0, fmaxf(s[nc][0], s[nc][1]));
            mx1 = fmaxf(mx1, fmaxf(s[nc][2], s[nc][3]));
        }
        mx0 = fmaxf(mx0, __shfl_xor_sync(0xffffffffu, mx0, 1));
        mx0 = fmaxf(mx0, __shfl_xor_sync(0xffffffffu, mx0, 2));
        mx1 = fmaxf(mx1, __shfl_xor_sync(0xffffffffu, mx1, 1));
        mx1 = fmaxf(mx1, __shfl_xor_sync(0xffffffffu, mx1, 2));
        float mn0 = fmaxf(m0v, mx0), mn1 = fmaxf(m1v, mx1);
        float c0 = ex2(m0v - mn0), c1 = ex2(m1v - mn1);
        float su0 = 0.f, su1 = 0.f;
        #pragma unroll
        for (int nc = 0; nc < 8; nc++) {
            s[nc][0] = ex2(s[nc][0] - mn0);
            s[nc][1] = ex2(s[nc][1] - mn0);
            s[nc][2] = ex2(s[nc][2] - mn1);
            s[nc][3] = ex2(s[nc][3] - mn1);
            su0 += s[nc][0] + s[nc][1];
            su1 += s[nc][2] + s[nc][3];
        }
        su0 += __shfl_xor_sync(0xffffffffu, su0, 1);
        su0 += __shfl_xor_sync(0xffffffffu, su0, 2);
        su1 += __shfl_xor_sync(0xffffffffu, su1, 1);
        su1 += __shfl_xor_sync(0xffffffffu, su1, 2);
        l0v = l0v * c0 + su0;
        l1v = l1v * c1 + su1;
        m0v = mn0; m1v = mn1;
        #pragma unroll
        for (int nc = 0; nc < 8; nc++) {
            acc[nc][0] *= c0; acc[nc][1] *= c0;
            acc[nc][2] *= c1; acc[nc][3] *= c1;
        }

        // ---- ctx += P V (3-MMA split), term-major issue order ----
        {
            uint32_t vfb[2][32];
            ld_vfr(vfb[0], kvb, vb_off, 0);
            #pragma unroll
            for (int ks = 0; ks < 4; ks++) {
                if (ks < 3) ld_vfr(vfb[(ks + 1) & 1], kvb, vb_off, ks + 1);
                uint32_t ph[4], pl[4];
                split2(s[2 * ks][0],     s[2 * ks][1],     ph[0], pl[0]);
                split2(s[2 * ks][2],     s[2 * ks][3],     ph[1], pl[1]);
                split2(s[2 * ks + 1][0], s[2 * ks + 1][1], ph[2], pl[2]);
                split2(s[2 * ks + 1][2], s[2 * ks + 1][3], ph[3], pl[3]);
                const uint32_t* vf = vfb[ks & 1];
                const uint32_t* vg = vf + 16;
                #pragma unroll
                for (int nc = 0; nc < 8; nc++)
                    mma16816(acc[nc], ph, vf + (nc >> 1) * 4 + (nc & 1) * 2);
                #pragma unroll
                for (int nc = 0; nc < 8; nc++)
                    mma16816(acc[nc], pl, vf + (nc >> 1) * 4 + (nc & 1) * 2);
                #pragma unroll
                for (int nc = 0; nc < 8; nc++)
                    mma16816(acc[nc], ph, vg + (nc >> 1) * 4 + (nc & 1) * 2);
            }
        }
    }

    float i0 = 1.f / l0v, i1 = 1.f / l1v;
    const int r0 = q0 + wid * 16 + (lane >> 2);
    const int cb = h * HDIM + 2 * (lane & 3);
    #pragma unroll
    for (int nc = 0; nc < 8; nc++) {
        int cc = cb + nc * 8;
        uint32_t ph, pl;
        split2(acc[nc][0] * i0, acc[nc][1] * i0, ph, pl);
        size_t off = (size_t)(b * SEQ + r0) * DMODEL + cc;
        *(uint32_t*)(chi + off) = ph;
        *(uint32_t*)(clo + off) = pl;
        split2(acc[nc][2] * i1, acc[nc][3] * i1, ph, pl);
        off = (size_t)(b * SEQ + r0 + 8) * DMODEL + cc;
        *(uint32_t*)(chi + off) = ph;
        *(uint32_t*)(clo + off) = pl;
    }
}

// ---------------------------------------------------------------------------
extern "C" void kernel_launch(void* const* d_in, const int* in_sizes, int n_in,
                              void* d_out, int out_size)
{
    (void)in_sizes; (void)n_in; (void)out_size;
    const float* x     = (const float*)d_in[0];
    const float* W_qkv = (const float*)d_in[1];
    const float* b_qkv = (const float*)d_in[2];
    const float* W_out = (const float*)d_in[3];
    float* out = (float*)d_out;

    bf *xhi, *xlo, *wqh, *wql, *woh, *wol, *chi, *clo;
    bf *qh, *ql, *kh, *kl, *vh, *vl;
    cudaGetSymbolAddress((void**)&xhi, g_xhi);
    cudaGetSymbolAddress((void**)&xlo, g_xlo);
    cudaGetSymbolAddress((void**)&wqh, g_wqh);
    cudaGetSymbolAddress((void**)&wql, g_wql);
    cudaGetSymbolAddress((void**)&woh, g_woh);
    cudaGetSymbolAddress((void**)&wol, g_wol);
    cudaGetSymbolAddress((void**)&chi, g_chi);
    cudaGetSymbolAddress((void**)&clo, g_clo);
    cudaGetSymbolAddress((void**)&qh, g_qh);
    cudaGetSymbolAddress((void**)&ql, g_ql);
    cudaGetSymbolAddress((void**)&kh, g_kh);
    cudaGetSymbolAddress((void**)&kl, g_kl);
    cudaGetSymbolAddress((void**)&vh, g_vh);
    cudaGetSymbolAddress((void**)&vl, g_vl);

    cudaFuncSetAttribute(gemm_hmma_x3<0>, cudaFuncAttributeMaxDynamicSharedMemorySize,
                         GM_DYN_BYTES);
    cudaFuncSetAttribute(gemm_hmma_x3<1>, cudaFuncAttributeMaxDynamicSharedMemorySize,
                         GM_DYN_BYTES);
    cudaFuncSetAttribute(flash_hmma, cudaFuncAttributeMaxDynamicSharedMemorySize,
                         ATT_SMEM);

    // fused pre-pass (one launch)
    prep_kernel<<<8192, 256>>>(x, W_qkv, W_out, xhi, xlo, wqh, wql, woh, wol);

    gemm_hmma_x3<1><<<dim3(QKV_N / 128, ROWS / 128), 512, GM_DYN_BYTES>>>(
        xhi, xlo, wqh, wql, b_qkv, nullptr,
        qh, ql, kh, kl, vh, vl, ROWS, QKV_N, DMODEL);

    flash_hmma<<<dim3(16, NHEAD, BATCH), 256, ATT_SMEM>>>(
        qh, ql, kh, kl, vh, vl, chi, clo);

    gemm_hmma_x3<0><<<dim3(DMODEL / 128, ROWS / 128), 512, GM_DYN_BYTES>>>(
        chi, clo, woh, wol, nullptr, out,
        nullptr, nullptr, nullptr, nullptr, nullptr, nullptr,
        ROWS, DMODEL, DMODEL);
}